// round 16
// baseline (speedup 1.0000x reference)
#include <cuda_runtime.h>
#include <math.h>
#include <stdint.h>

#define BATCH 64
#define NG    32
#define CIN   128
#define COUT  128
#define LMAX  16
#define NR    (BATCH*LMAX*2)   // 2048 rows (b,m,ri)

// ---------------- scratch (device globals; no allocation allowed) ----------
__device__ float g_F[(size_t)BATCH*LMAX*2*NG*CIN];     // [b][m][ri][j][i]
// coef/chat layout: [l][m][ri][b][c]  -> valid region per l = first (l+1)*128 rows
__device__ float g_coef[(size_t)LMAX*2048*CIN];
__device__ float g_chat[(size_t)LMAX*2048*COUT];
__device__ float g_G[(size_t)BATCH*NG*LMAX*2*COUT];    // [b][j][m][ri][o]
__device__ float g_Qw[LMAX*LMAX*NG];                   // [l][m][j] * wj * s_l
__device__ float g_Qs[LMAX*LMAX*NG];                   // [l][m][j] * k_m
__device__ float g_cosT[LMAX*NG];                      // [m][p]
__device__ float g_sinT[LMAX*NG];

// kC smem geometry (floats)
#define APAD 132
#define BPAD 136
#define SM_A_FLOATS (128*APAD)
#define SM_B_FLOATS (128*BPAD)
#define SM_C_BYTES  ((SM_A_FLOATS + SM_B_FLOATS) * 4)   // 137216

// kA/kE smem geometry
#define TP 36    // 32x32 table pad: banks 4g+tg distinct
#define XP 136   // 32x128 data pad: banks 8tg+g distinct

__device__ __forceinline__ float to_tf32(float x) {
    float r;
    asm("cvt.rna.tf32.f32 %0, %1;" : "=f"(r) : "f"(x));
    return r;
}

#define MMA_TF32(acc, a, b0, b1)                                          \
    asm volatile(                                                         \
        "mma.sync.aligned.m16n8k8.row.col.f32.tf32.tf32.f32 "             \
        "{%0,%1,%2,%3}, {%4,%5,%6,%7}, {%8,%9}, {%0,%1,%2,%3};"           \
        : "+f"((acc)[0]), "+f"((acc)[1]), "+f"((acc)[2]), "+f"((acc)[3])  \
        : "r"((a)[0]), "r"((a)[1]), "r"((a)[2]), "r"((a)[3]),             \
          "r"(b0), "r"(b1))

// ---------------- init: Legendre + trig tables, fp32, 512-way parallel -----
__global__ void init_tables() {
    int t = threadIdx.x;                  // 0..511
    int m = t >> 5, j = t & 31;           // one thread per (m, j)
    float sx, cx;
    sincospif((j + 0.5f) / NG, &sx, &cx);
    float wj = sx * ((float)M_PI / NG) * (2.0f * (float)M_PI / NG);

    for (int l = 0; l < m; l++) {
        g_Qw[(l*LMAX + m)*NG + j] = 0.f;
        g_Qs[(l*LMAX + m)*NG + j] = 0.f;
    }

    float Pmm = 1.0f, invf = 1.0f;
    for (int mm = 1; mm <= m; mm++) Pmm = -(2.0f*mm - 1.0f) * sx * Pmm;
    for (int tt = 1; tt <= 2*m; tt++) invf /= (float)tt;
    float rat = invf;
    float pl_2 = 0.0f, pl_1 = 0.0f, pl = 0.0f;
    const float inv4pi = 1.0f / (4.0f * (float)M_PI);
    for (int l = m; l < LMAX; l++) {
        if (l == m)        pl = Pmm;
        else if (l == m+1) pl = (2.0f*m + 1.0f) * cx * Pmm;
        else               pl = ((2.0f*l - 1.0f)*cx*pl_1 - (l + m - 1.0f)*pl_2) / (float)(l - m);
        float Nlm = sqrtf((2.0f*l + 1.0f) * inv4pi * rat);
        float q   = Nlm * pl;
        float sl  = 2.0f*(float)M_PI * sqrtf(4.0f*(float)M_PI / (2.0f*l + 1.0f));
        float km  = (m == 0) ? 1.0f : 2.0f;
        g_Qw[(l*LMAX + m)*NG + j] = q * wj * sl;
        g_Qs[(l*LMAX + m)*NG + j] = q * km;
        pl_2 = pl_1; pl_1 = pl;
        rat *= (float)(l + 1 - m) / (float)(l + 1 + m);
    }

    float sa, ca;
    sincospif(2.0f * (float)m * (float)j / (float)NG, &sa, &ca);
    g_cosT[m*NG + j] = ca;
    g_sinT[m*NG + j] = sa;
}

// ---------------- A: phi DFT as tensor GEMM per (b,j) ----------------------
// F[mr;c] = T[mr;p] * X[p;c], M=32, N=128, K=32; T[2m][p]=cos, T[2m+1][p]=-sin
__global__ void __launch_bounds__(64) kA(const float* __restrict__ in) {
    __shared__ float Ts[32*TP];
    __shared__ float Xs[32*XP];
    int bj = blockIdx.x;                  // b*32 + j
    int b = bj >> 5, j = bj & 31;
    int t = threadIdx.x;

#pragma unroll
    for (int e = 0; e < 16; e++) {
        int idx = t + e*64;               // 0..1023
        int mr = idx >> 5, p = idx & 31;
        int m = mr >> 1;
        float v = (mr & 1) ? -g_sinT[m*NG + p] : g_cosT[m*NG + p];
        Ts[mr*TP + p] = to_tf32(v);
    }
    const float4* src = (const float4*)(in + (size_t)bj * 4096);
#pragma unroll
    for (int e = 0; e < 16; e++) {
        int idx = t + e*64;               // p = idx>>5, c4 = idx&31
        float4 v = src[idx];
        float* d = &Xs[(idx >> 5)*XP + (idx & 31)*4];
        d[0]=to_tf32(v.x); d[1]=to_tf32(v.y); d[2]=to_tf32(v.z); d[3]=to_tf32(v.w);
    }
    __syncthreads();

    int wid = t >> 5, lane = t & 31;
    int g = lane >> 2, tg = lane & 3;
    int cbase = wid * 64;

    float acc[2][8][4] = {};
    const uint32_t* Tu = (const uint32_t*)Ts;
    const uint32_t* Xu = (const uint32_t*)Xs;
#pragma unroll
    for (int ks = 0; ks < 4; ks++) {
        int k0 = ks*8;
        uint32_t a[2][4];
#pragma unroll
        for (int mf = 0; mf < 2; mf++) {
            int r0 = mf*16;
            a[mf][0] = Tu[(r0 + g    )*TP + k0 + tg    ];
            a[mf][1] = Tu[(r0 + g + 8)*TP + k0 + tg    ];
            a[mf][2] = Tu[(r0 + g    )*TP + k0 + tg + 4];
            a[mf][3] = Tu[(r0 + g + 8)*TP + k0 + tg + 4];
        }
#pragma unroll
        for (int nf = 0; nf < 8; nf++) {
            int c0 = cbase + nf*8 + g;
            uint32_t b0 = Xu[(k0 + tg    )*XP + c0];
            uint32_t b1 = Xu[(k0 + tg + 4)*XP + c0];
            MMA_TF32(acc[0][nf], a[0], b0, b1);
            MMA_TF32(acc[1][nf], a[1], b0, b1);
        }
    }
    // F addr = b*131072 + mr*4096 + j*128 + c
    float* Fb = g_F + (size_t)b*131072 + (size_t)j*128;
#pragma unroll
    for (int mf = 0; mf < 2; mf++) {
        int r0 = mf*16 + g;
#pragma unroll
        for (int nf = 0; nf < 8; nf++) {
            int c = cbase + nf*8 + tg*2;
            *(float2*)&Fb[(size_t)r0*4096 + c] =
                make_float2(acc[mf][nf][0], acc[mf][nf][1]);
            *(float2*)&Fb[(size_t)(r0+8)*4096 + c] =
                make_float2(acc[mf][nf][2], acc[mf][nf][3]);
        }
    }
}

// ---------------- B: Legendre analysis with reflection symmetry ------------
__global__ void __launch_bounds__(64) kB() {
    int r = blockIdx.x;                   // (b*16+m)*2+ri
    int b = r >> 5, m = (r >> 1) & 15, ri = r & 1;
    int t = threadIdx.x;
    __shared__ float sq[16][16];          // Qw[l][m][j], j<16
    for (int q = t; q < 256; q += 64) {
        int l = q >> 4, j = q & 15;
        sq[l][j] = g_Qw[(l*LMAX + m)*NG + j];
    }
    __syncthreads();

    const float2* src = (const float2*)g_F + (size_t)r * NG * 64 + t;
    float2 fe[16], fo[16];
#pragma unroll
    for (int j = 0; j < 16; j++) {
        float2 a = src[j*64], c = src[(31-j)*64];
        fe[j] = make_float2(a.x + c.x, a.y + c.y);
        fo[j] = make_float2(a.x - c.x, a.y - c.y);
    }

    float2* Cout = (float2*)g_coef;
    size_t rowbase = (size_t)(m*2 + ri)*64 + b;   // within-l row offset
    if ((m & 1) == 0) {
#pragma unroll
        for (int l = 0; l < 16; l++) {
            if (l < m) continue;
            float2 acc = make_float2(0.f, 0.f);
#pragma unroll
            for (int j = 0; j < 16; j++) {
                float q = sq[l][j];
                float2 f = (l & 1) ? fo[j] : fe[j];
                acc.x += q*f.x; acc.y += q*f.y;
            }
            Cout[((size_t)l*2048 + rowbase)*64 + t] = acc;
        }
    } else {
#pragma unroll
        for (int l = 0; l < 16; l++) {
            if (l < m) continue;
            float2 acc = make_float2(0.f, 0.f);
#pragma unroll
            for (int j = 0; j < 16; j++) {
                float q = sq[l][j];
                float2 f = (l & 1) ? fe[j] : fo[j];
                acc.x += q*f.x; acc.y += q*f.y;
            }
            Cout[((size_t)l*2048 + rowbase)*64 + t] = acc;
        }
    }
}

// ---------------- C: per-degree channel mix on tensor cores (tf32 mma) -----
__global__ void __launch_bounds__(256) kC(const float* __restrict__ w) {
    int l = blockIdx.y, mt = blockIdx.x;
    if (mt > l) return;                   // zero region: skip
    extern __shared__ float sm[];
    float* As = sm;                       // [128][APAD]
    float* Bs = sm + SM_A_FLOATS;         // [128][BPAD]

    const float* A = g_coef + ((size_t)l*2048 + (size_t)mt*128)*CIN;
    const float* B = w + l*COUT;
    float* C = g_chat + ((size_t)l*2048 + (size_t)mt*128)*COUT;

    int tid = threadIdx.x;
#pragma unroll
    for (int e = 0; e < 16; e++) {
        int lin = tid + e*256;
        int row = lin >> 5, c4 = lin & 31;
        float4 va = *(const float4*)&A[row*CIN + c4*4];
        float* d = &As[row*APAD + c4*4];
        d[0] = to_tf32(va.x); d[1] = to_tf32(va.y);
        d[2] = to_tf32(va.z); d[3] = to_tf32(va.w);
        float4 vb = *(const float4*)&B[(size_t)row*(LMAX*COUT) + c4*4];
        float* db = &Bs[row*BPAD + c4*4];
        db[0] = to_tf32(vb.x); db[1] = to_tf32(vb.y);
        db[2] = to_tf32(vb.z); db[3] = to_tf32(vb.w);
    }
    __syncthreads();

    int wid = tid >> 5, lane = tid & 31;
    int g = lane >> 2, tg = lane & 3;
    int wm = wid & 3, wn = wid >> 2;
    int rbase = wm*32, cbase = wn*64;

    float acc[2][8][4];
#pragma unroll
    for (int mf = 0; mf < 2; mf++)
#pragma unroll
        for (int nf = 0; nf < 8; nf++)
#pragma unroll
            for (int q = 0; q < 4; q++) acc[mf][nf][q] = 0.f;

    const uint32_t* Au = (const uint32_t*)As;
    const uint32_t* Bu = (const uint32_t*)Bs;

#pragma unroll
    for (int ks = 0; ks < 16; ks++) {
        int k0 = ks*8;
        uint32_t a[2][4];
#pragma unroll
        for (int mf = 0; mf < 2; mf++) {
            int r0 = rbase + mf*16;
            a[mf][0] = Au[(r0 + g    )*APAD + k0 + tg    ];
            a[mf][1] = Au[(r0 + g + 8)*APAD + k0 + tg    ];
            a[mf][2] = Au[(r0 + g    )*APAD + k0 + tg + 4];
            a[mf][3] = Au[(r0 + g + 8)*APAD + k0 + tg + 4];
        }
#pragma unroll
        for (int nf = 0; nf < 8; nf++) {
            int c0 = cbase + nf*8 + g;
            uint32_t b0 = Bu[(k0 + tg    )*BPAD + c0];
            uint32_t b1 = Bu[(k0 + tg + 4)*BPAD + c0];
            MMA_TF32(acc[0][nf], a[0], b0, b1);
            MMA_TF32(acc[1][nf], a[1], b0, b1);
        }
    }

#pragma unroll
    for (int mf = 0; mf < 2; mf++) {
        int r0 = rbase + mf*16 + g;
#pragma unroll
        for (int nf = 0; nf < 8; nf++) {
            int c0 = cbase + nf*8 + tg*2;
            *(float2*)&C[(size_t)r0*COUT + c0] =
                make_float2(acc[mf][nf][0], acc[mf][nf][1]);
            *(float2*)&C[(size_t)(r0 + 8)*COUT + c0] =
                make_float2(acc[mf][nf][2], acc[mf][nf][3]);
        }
    }
}

// ---------------- D: Legendre synthesis with reflection symmetry -----------
__global__ void __launch_bounds__(64) kD() {
    int r = blockIdx.x;                   // (b*16+m)*2+ri
    int ri = r & 1, m = (r >> 1) & 15, b = r >> 5;
    int t = threadIdx.x;
    __shared__ float sq[16][16];          // Qs[l][m][j], j<16 (incl. k_m)
    for (int q = t; q < 256; q += 64) {
        int l = q >> 4, j = q & 15;
        sq[l][j] = g_Qs[(l*LMAX + m)*NG + j];
    }
    __syncthreads();

    float2 ch[16];
    const float2* src = (const float2*)g_chat;
    size_t rowbase = (size_t)(m*2 + ri)*64 + b;
#pragma unroll
    for (int l = 0; l < 16; l++)
        ch[l] = (l >= m) ? src[((size_t)l*2048 + rowbase)*64 + t]
                         : make_float2(0.f, 0.f);

    float2* Gout = (float2*)g_G;
    size_t gbase = ((((size_t)b*NG)*16 + m)*2 + ri)*64 + t;
    const size_t jstride = (size_t)16*2*64;

    if ((m & 1) == 0) {
#pragma unroll
        for (int j = 0; j < 16; j++) {
            float2 Ge = make_float2(0.f,0.f), Go = make_float2(0.f,0.f);
#pragma unroll
            for (int l = 0; l < 16; l++) {
                float q = sq[l][j];
                if (l & 1) { Go.x += q*ch[l].x; Go.y += q*ch[l].y; }
                else       { Ge.x += q*ch[l].x; Ge.y += q*ch[l].y; }
            }
            Gout[gbase + (size_t)j*jstride]      = make_float2(Ge.x+Go.x, Ge.y+Go.y);
            Gout[gbase + (size_t)(31-j)*jstride] = make_float2(Ge.x-Go.x, Ge.y-Go.y);
        }
    } else {
#pragma unroll
        for (int j = 0; j < 16; j++) {
            float2 Ge = make_float2(0.f,0.f), Go = make_float2(0.f,0.f);
#pragma unroll
            for (int l = 0; l < 16; l++) {
                float q = sq[l][j];
                if (l & 1) { Ge.x += q*ch[l].x; Ge.y += q*ch[l].y; }
                else       { Go.x += q*ch[l].x; Go.y += q*ch[l].y; }
            }
            Gout[gbase + (size_t)j*jstride]      = make_float2(Ge.x+Go.x, Ge.y+Go.y);
            Gout[gbase + (size_t)(31-j)*jstride] = make_float2(Ge.x-Go.x, Ge.y-Go.y);
        }
    }
}

// ---------------- E: inverse phi DFT as tensor GEMM per (b,j) + bias -------
// out[p;c] = Ti[p;mr] * G[mr;c] + bias[c], Ti[p][mr] = T[mr][p]
__global__ void __launch_bounds__(64) kE(const float* __restrict__ bias,
                                         float* __restrict__ out) {
    __shared__ float Ts[32*TP];
    __shared__ float Gs[32*XP];
    int bj = blockIdx.x;
    int t = threadIdx.x;

#pragma unroll
    for (int e = 0; e < 16; e++) {
        int idx = t + e*64;               // p = idx>>5, mr = idx&31
        int p = idx >> 5, mr = idx & 31;
        int m = mr >> 1;
        float v = (mr & 1) ? -g_sinT[m*NG + p] : g_cosT[m*NG + p];
        Ts[p*TP + mr] = to_tf32(v);
    }
    const float4* src = (const float4*)(g_G + (size_t)bj * 4096);
#pragma unroll
    for (int e = 0; e < 16; e++) {
        int idx = t + e*64;               // mr = idx>>5, c4 = idx&31
        float4 v = src[idx];
        float* d = &Gs[(idx >> 5)*XP + (idx & 31)*4];
        d[0]=to_tf32(v.x); d[1]=to_tf32(v.y); d[2]=to_tf32(v.z); d[3]=to_tf32(v.w);
    }
    __syncthreads();

    int wid = t >> 5, lane = t & 31;
    int g = lane >> 2, tg = lane & 3;
    int cbase = wid * 64;

    float acc[2][8][4] = {};
    const uint32_t* Tu = (const uint32_t*)Ts;
    const uint32_t* Gu = (const uint32_t*)Gs;
#pragma unroll
    for (int ks = 0; ks < 4; ks++) {
        int k0 = ks*8;
        uint32_t a[2][4];
#pragma unroll
        for (int mf = 0; mf < 2; mf++) {
            int r0 = mf*16;
            a[mf][0] = Tu[(r0 + g    )*TP + k0 + tg    ];
            a[mf][1] = Tu[(r0 + g + 8)*TP + k0 + tg    ];
            a[mf][2] = Tu[(r0 + g    )*TP + k0 + tg + 4];
            a[mf][3] = Tu[(r0 + g + 8)*TP + k0 + tg + 4];
        }
#pragma unroll
        for (int nf = 0; nf < 8; nf++) {
            int c0 = cbase + nf*8 + g;
            uint32_t b0 = Gu[(k0 + tg    )*XP + c0];
            uint32_t b1 = Gu[(k0 + tg + 4)*XP + c0];
            MMA_TF32(acc[0][nf], a[0], b0, b1);
            MMA_TF32(acc[1][nf], a[1], b0, b1);
        }
    }
    // out addr = bj*4096 + p*128 + c, plus bias
    float* Ob = out + (size_t)bj * 4096;
#pragma unroll
    for (int nf = 0; nf < 8; nf++) {
        int c = cbase + nf*8 + tg*2;
        float2 bv = *(const float2*)&bias[c];
#pragma unroll
        for (int mf = 0; mf < 2; mf++) {
            int r0 = mf*16 + g;
            *(float2*)&Ob[(size_t)r0*128 + c] =
                make_float2(acc[mf][nf][0] + bv.x, acc[mf][nf][1] + bv.y);
            *(float2*)&Ob[(size_t)(r0+8)*128 + c] =
                make_float2(acc[mf][nf][2] + bv.x, acc[mf][nf][3] + bv.y);
        }
    }
}

extern "C" void kernel_launch(void* const* d_in, const int* in_sizes, int n_in,
                              void* d_out, int out_size) {
    const float* in   = (const float*)d_in[0];
    const float* w    = (const float*)d_in[1];
    const float* bias = (const float*)d_in[2];
    float* out = (float*)d_out;

    cudaFuncSetAttribute(kC, cudaFuncAttributeMaxDynamicSharedMemorySize, SM_C_BYTES);

    init_tables<<<1, 512>>>();
    kA<<<BATCH*NG, 64>>>(in);
    kB<<<NR, 64>>>();
    kC<<<dim3(16, LMAX), 256, SM_C_BYTES>>>(w);
    kD<<<NR, 64>>>();
    kE<<<BATCH*NG, 64>>>(bias, out);
}